// round 9
// baseline (speedup 1.0000x reference)
#include <cuda_runtime.h>
#include <cuda_bf16.h>
#include <math.h>
#include <stdint.h>

#define N_NODE   100000
#define N_EDGE   500000
#define IN_DIM   128
#define OUT_DIM  128
#define ATTN_DIM 64
#define N_RELTAB 401
#define N_Q      64
#define N_TAU    366
#define SCAN_B   1024
#define N_SCANB  ((N_NODE + SCAN_B - 1) / SCAN_B)   // 98

// ---------------- scratch (no allocs allowed) ----------------
__device__ float d_hsW[N_NODE * ATTN_DIM];
__device__ float d_hrW[N_RELTAB * ATTN_DIM];
__device__ float d_qW[N_Q * ATTN_DIM];
__device__ float d_tauW[N_TAU * ATTN_DIM];
__device__ float d_tauTab[N_TAU * IN_DIM];
__device__ float d_agg[N_NODE * IN_DIM];
__device__ float d_agg_s[N_NODE * IN_DIM];

// sort-by-obj machinery
__device__ int d_counts[N_NODE];
__device__ int d_offsets[N_NODE];
__device__ int d_cursor[N_NODE];
__device__ int d_blockSums[N_SCANB + 2];
__device__ int4 d_esort[N_EDGE];         // sorted {sub, rel, t, r_idx}

// pre-converted bf16 hi/lo weight images, padded to SMEM stride
__device__ __nv_bfloat16 d_Wh_hi[128 * 136];
__device__ __nv_bfloat16 d_Wh_lo[128 * 136];
__device__ __nv_bfloat16 d_Whs_hi[128 * 136];
__device__ __nv_bfloat16 d_Whs_lo[128 * 136];
__device__ __nv_bfloat16 d_Ws_hi[128 * 72];
__device__ __nv_bfloat16 d_Ws_lo[128 * 72];

// ---------------- helpers ----------------
__device__ __forceinline__ uint32_t smem_u32(const void* p) {
    uint32_t a;
    asm("{ .reg .u64 t; cvta.to.shared.u64 t, %1; cvt.u32.u64 %0, t; }" : "=r"(a) : "l"(p));
    return a;
}

#define LDSM_X4(r0, r1, r2, r3, addr) \
    asm volatile("ldmatrix.sync.aligned.m8n8.x4.shared.b16 {%0,%1,%2,%3}, [%4];" \
                 : "=r"(r0), "=r"(r1), "=r"(r2), "=r"(r3) : "r"(addr))
#define LDSM_X2T(r0, r1, addr) \
    asm volatile("ldmatrix.sync.aligned.m8n8.x2.trans.shared.b16 {%0,%1}, [%2];" \
                 : "=r"(r0), "=r"(r1) : "r"(addr))
#define MMA16816(c, a0, a1, a2, a3, b0, b1) \
    asm volatile("mma.sync.aligned.m16n8k16.row.col.f32.bf16.bf16.f32 " \
                 "{%0,%1,%2,%3}, {%4,%5,%6,%7}, {%8,%9}, {%0,%1,%2,%3};" \
                 : "+f"((c)[0]), "+f"((c)[1]), "+f"((c)[2]), "+f"((c)[3]) \
                 : "r"(a0), "r"(a1), "r"(a2), "r"(a3), "r"(b0), "r"(b1))

// ---------------- build the small tables ----------------
__global__ void table_kernel(const float* __restrict__ rela,
                             const int*   __restrict__ q_rel,
                             const int*   __restrict__ q_tau_p,
                             const float* __restrict__ Wr,
                             const float* __restrict__ Wqr,
                             const float* __restrict__ Wqr_b,
                             const float* __restrict__ Wtau,
                             const float* __restrict__ w_t1,
                             const float* __restrict__ b_t1,
                             const float* __restrict__ w_t2,
                             const float* __restrict__ b_t2) {
    __shared__ float s[IN_DIM];
    int b   = blockIdx.x;
    int tid = threadIdx.x;

    const float* W = nullptr;
    float* outrow  = nullptr;
    bool  add_bias = false;

    if (b < N_RELTAB) {
        s[tid] = rela[(size_t)b * IN_DIM + tid];
        W = Wr; outrow = d_hrW + b * ATTN_DIM;
    } else if (b < N_RELTAB + N_Q) {
        int r = b - N_RELTAB;
        s[tid] = rela[(size_t)q_rel[r] * IN_DIM + tid];
        W = Wqr; outrow = d_qW + r * ATTN_DIM; add_bias = true;
    } else {
        int t = b - N_RELTAB - N_Q;
        float delta = (float)(t - *q_tau_p);
        float v = w_t1[tid] * delta + b_t1[tid] + sinf(w_t2[tid] * delta + b_t2[tid]);
        s[tid] = v;
        d_tauTab[(size_t)t * IN_DIM + tid] = v;
        W = Wtau; outrow = d_tauW + t * ATTN_DIM;
    }
    __syncthreads();

    if (tid < ATTN_DIM) {
        float acc = add_bias ? Wqr_b[tid] : 0.f;
        #pragma unroll 8
        for (int k = 0; k < IN_DIM; k++)
            acc = fmaf(s[k], W[k * ATTN_DIM + tid], acc);
        outrow[tid] = acc;
    }
}

// ---------------- weight prep ----------------
__global__ void wprep_kernel(const float* __restrict__ Wh,
                             const float* __restrict__ Whs,
                             const float* __restrict__ Ws) {
    int k = blockIdx.x;
    int t = threadIdx.x;

    float w1 = (t < 128) ? Wh[k * 128 + t]  : 0.f;
    __nv_bfloat16 h1 = __float2bfloat16(w1);
    d_Wh_hi[k * 136 + t] = h1;
    d_Wh_lo[k * 136 + t] = __float2bfloat16(w1 - __bfloat162float(h1));

    float w2 = (t < 128) ? Whs[k * 128 + t] : 0.f;
    __nv_bfloat16 h2 = __float2bfloat16(w2);
    d_Whs_hi[k * 136 + t] = h2;
    d_Whs_lo[k * 136 + t] = __float2bfloat16(w2 - __bfloat162float(h2));

    if (t < 72) {
        float w3 = (t < 64) ? Ws[k * 64 + t] : 0.f;
        __nv_bfloat16 h3 = __float2bfloat16(w3);
        d_Ws_hi[k * 72 + t] = h3;
        d_Ws_lo[k * 72 + t] = __float2bfloat16(w3 - __bfloat162float(h3));
    }
}

// ---------------- counting sort of edges by obj ----------------
__global__ void hist_kernel(const int* __restrict__ edges) {
    int i = blockIdx.x * blockDim.x + threadIdx.x;
    if (i < N_EDGE) atomicAdd(&d_counts[edges[(size_t)i * 7 + 6]], 1);
}
__global__ void scan1_kernel() {
    __shared__ int sh[SCAN_B];
    int gid = blockIdx.x * SCAN_B + threadIdx.x;
    int v = (gid < N_NODE) ? d_counts[gid] : 0;
    sh[threadIdx.x] = v;
    __syncthreads();
    #pragma unroll
    for (int off = 1; off < SCAN_B; off <<= 1) {
        int t = (threadIdx.x >= off) ? sh[threadIdx.x - off] : 0;
        __syncthreads();
        sh[threadIdx.x] += t;
        __syncthreads();
    }
    if (gid < N_NODE) d_offsets[gid] = sh[threadIdx.x] - v;
    if (threadIdx.x == SCAN_B - 1) d_blockSums[blockIdx.x] = sh[SCAN_B - 1];
}
// fused: each block computes its own block-prefix from raw block sums
__global__ void scan3_kernel() {
    __shared__ int bpref;
    if (threadIdx.x < 32) {
        int s = 0;
        for (int j = threadIdx.x; j < blockIdx.x; j += 32) s += d_blockSums[j];
        #pragma unroll
        for (int o = 16; o; o >>= 1) s += __shfl_xor_sync(0xffffffffu, s, o);
        if (threadIdx.x == 0) bpref = s;
    }
    __syncthreads();
    int gid = blockIdx.x * SCAN_B + threadIdx.x;
    if (gid < N_NODE) {
        int o = d_offsets[gid] + bpref;
        d_offsets[gid] = o;
        d_cursor[gid]  = o;
    }
}
// fill: read edge row once (coalesced), write full sorted record
__global__ void fill_kernel(const int* __restrict__ edges,
                            const int* __restrict__ q_tau_p) {
    int i = blockIdx.x * blockDim.x + threadIdx.x;
    if (i < N_EDGE) {
        const int* e = edges + (size_t)i * 7;
        int r_idx = e[0];
        int rel   = e[2];
        int tau   = e[4];
        int sub   = e[5];
        int obj   = e[6];
        int t = (tau >= 0) ? tau : *q_tau_p;
        int pos = atomicAdd(&d_cursor[obj], 1);
        d_esort[pos] = make_int4(sub, rel, t, r_idx);
    }
}

// ---------------- fused aggregation: alpha inline, one warp per node -----
__global__ void __launch_bounds__(256)
agg_kernel(const float* __restrict__ hidden,
           const float* __restrict__ rela,
           const float* __restrict__ w_alpha,
           const float* __restrict__ w_alpha_b) {
    int node = (blockIdx.x * blockDim.x + threadIdx.x) >> 5;
    int lane = threadIdx.x & 31;
    if (node >= N_NODE) return;

    int start = d_offsets[node];
    int cnt   = d_counts[node];

    float2 wa = *reinterpret_cast<const float2*>(w_alpha + lane * 2);
    float  wb = w_alpha_b[0];

    float4 a1 = make_float4(0.f, 0.f, 0.f, 0.f);
    float4 a2 = make_float4(0.f, 0.f, 0.f, 0.f);

    int i = 0;
    for (; i + 2 <= cnt; i += 2) {
        int4 e0 = __ldg(&d_esort[start + i]);
        int4 e1 = __ldg(&d_esort[start + i + 1]);

        // attention gathers (float2 per lane over 64 dims)
        float2 h0 = *reinterpret_cast<const float2*>(d_hsW + (size_t)e0.x * ATTN_DIM + lane * 2);
        float2 h1 = *reinterpret_cast<const float2*>(d_hsW + (size_t)e1.x * ATTN_DIM + lane * 2);
        float2 r0 = *reinterpret_cast<const float2*>(d_hrW + e0.y * ATTN_DIM + lane * 2);
        float2 r1 = *reinterpret_cast<const float2*>(d_hrW + e1.y * ATTN_DIM + lane * 2);
        float2 t0 = *reinterpret_cast<const float2*>(d_tauW + e0.z * ATTN_DIM + lane * 2);
        float2 t1 = *reinterpret_cast<const float2*>(d_tauW + e1.z * ATTN_DIM + lane * 2);
        float2 q0 = *reinterpret_cast<const float2*>(d_qW + e0.w * ATTN_DIM + lane * 2);
        float2 q1 = *reinterpret_cast<const float2*>(d_qW + e1.w * ATTN_DIM + lane * 2);

        // message gathers (float4 per lane over 128 dims)
        float4 hs0 = *reinterpret_cast<const float4*>(hidden + (size_t)e0.x * IN_DIM + lane * 4);
        float4 hs1 = *reinterpret_cast<const float4*>(hidden + (size_t)e1.x * IN_DIM + lane * 4);
        float4 hr0 = *reinterpret_cast<const float4*>(rela   + (size_t)e0.y * IN_DIM + lane * 4);
        float4 hr1 = *reinterpret_cast<const float4*>(rela   + (size_t)e1.y * IN_DIM + lane * 4);
        float4 ht0 = *reinterpret_cast<const float4*>(d_tauTab + (size_t)e0.z * IN_DIM + lane * 4);
        float4 ht1 = *reinterpret_cast<const float4*>(d_tauTab + (size_t)e1.z * IN_DIM + lane * 4);

        float s0 = fmaxf(h0.x + r0.x + q0.x + t0.x, 0.f) * wa.x
                 + fmaxf(h0.y + r0.y + q0.y + t0.y, 0.f) * wa.y;
        float s1 = fmaxf(h1.x + r1.x + q1.x + t1.x, 0.f) * wa.x
                 + fmaxf(h1.y + r1.y + q1.y + t1.y, 0.f) * wa.y;
        #pragma unroll
        for (int o = 16; o; o >>= 1) {
            s0 += __shfl_xor_sync(0xffffffffu, s0, o);
            s1 += __shfl_xor_sync(0xffffffffu, s1, o);
        }
        float av0 = 1.f / (1.f + expf(-(s0 + wb)));
        float av1 = 1.f / (1.f + expf(-(s1 + wb)));

        float mx0 = hs0.x + hr0.x + ht0.x, my0 = hs0.y + hr0.y + ht0.y;
        float mz0 = hs0.z + hr0.z + ht0.z, mw0 = hs0.w + hr0.w + ht0.w;
        float mx1 = hs1.x + hr1.x + ht1.x, my1 = hs1.y + hr1.y + ht1.y;
        float mz1 = hs1.z + hr1.z + ht1.z, mw1 = hs1.w + hr1.w + ht1.w;

        a1.x = fmaf(av0, mx0, fmaf(av1, mx1, a1.x));
        a1.y = fmaf(av0, my0, fmaf(av1, my1, a1.y));
        a1.z = fmaf(av0, mz0, fmaf(av1, mz1, a1.z));
        a1.w = fmaf(av0, mw0, fmaf(av1, mw1, a1.w));
        a2.x += (mx0 - av0 * mx0) + (mx1 - av1 * mx1);
        a2.y += (my0 - av0 * my0) + (my1 - av1 * my1);
        a2.z += (mz0 - av0 * mz0) + (mz1 - av1 * mz1);
        a2.w += (mw0 - av0 * mw0) + (mw1 - av1 * mw1);
    }
    if (i < cnt) {
        int4 e0 = __ldg(&d_esort[start + i]);
        float2 h0 = *reinterpret_cast<const float2*>(d_hsW + (size_t)e0.x * ATTN_DIM + lane * 2);
        float2 r0 = *reinterpret_cast<const float2*>(d_hrW + e0.y * ATTN_DIM + lane * 2);
        float2 t0 = *reinterpret_cast<const float2*>(d_tauW + e0.z * ATTN_DIM + lane * 2);
        float2 q0 = *reinterpret_cast<const float2*>(d_qW + e0.w * ATTN_DIM + lane * 2);
        float4 hs0 = *reinterpret_cast<const float4*>(hidden + (size_t)e0.x * IN_DIM + lane * 4);
        float4 hr0 = *reinterpret_cast<const float4*>(rela   + (size_t)e0.y * IN_DIM + lane * 4);
        float4 ht0 = *reinterpret_cast<const float4*>(d_tauTab + (size_t)e0.z * IN_DIM + lane * 4);

        float s0 = fmaxf(h0.x + r0.x + q0.x + t0.x, 0.f) * wa.x
                 + fmaxf(h0.y + r0.y + q0.y + t0.y, 0.f) * wa.y;
        #pragma unroll
        for (int o = 16; o; o >>= 1) s0 += __shfl_xor_sync(0xffffffffu, s0, o);
        float av0 = 1.f / (1.f + expf(-(s0 + wb)));

        float mx0 = hs0.x + hr0.x + ht0.x, my0 = hs0.y + hr0.y + ht0.y;
        float mz0 = hs0.z + hr0.z + ht0.z, mw0 = hs0.w + hr0.w + ht0.w;
        a1.x = fmaf(av0, mx0, a1.x); a1.y = fmaf(av0, my0, a1.y);
        a1.z = fmaf(av0, mz0, a1.z); a1.w = fmaf(av0, mw0, a1.w);
        a2.x += mx0 - av0 * mx0; a2.y += my0 - av0 * my0;
        a2.z += mz0 - av0 * mz0; a2.w += mw0 - av0 * mw0;
    }

    *reinterpret_cast<float4*>(d_agg   + (size_t)node * IN_DIM + lane * 4) = a1;
    *reinterpret_cast<float4*>(d_agg_s + (size_t)node * IN_DIM + lane * 4) = a2;
}

// ---------------- GEMM tile helpers ----------------
__device__ __forceinline__ void load_A_regs(const float* __restrict__ A, int row0,
                                            int tid, int M, float4* v) {
    int row  = tid >> 2;
    int q    = tid & 3;
    int grow = row0 + row;
    bool valid = grow < M;
    const float4* src = reinterpret_cast<const float4*>(A + (size_t)grow * 128 + q * 32);
    #pragma unroll
    for (int j = 0; j < 8; j++)
        v[j] = valid ? src[j] : make_float4(0.f, 0.f, 0.f, 0.f);
}

__device__ __forceinline__ void sts_A(char* smem, int offAH, int offAL,
                                      int tid, const float4* v) {
    constexpr int SA_STR = 136;
    int row = tid >> 2;
    int q   = tid & 3;
    #pragma unroll
    for (int j = 0; j < 8; j++) {
        float4 x = v[j];
        uint32_t h01, h23, l01, l23;
        asm("cvt.rn.bf16x2.f32 %0, %1, %2;" : "=r"(h01) : "f"(x.y), "f"(x.x));
        asm("cvt.rn.bf16x2.f32 %0, %1, %2;" : "=r"(h23) : "f"(x.w), "f"(x.z));
        float r0 = x.x - __uint_as_float(h01 << 16);
        float r1 = x.y - __uint_as_float(h01 & 0xffff0000u);
        float r2 = x.z - __uint_as_float(h23 << 16);
        float r3 = x.w - __uint_as_float(h23 & 0xffff0000u);
        asm("cvt.rn.bf16x2.f32 %0, %1, %2;" : "=r"(l01) : "f"(r1), "f"(r0));
        asm("cvt.rn.bf16x2.f32 %0, %1, %2;" : "=r"(l23) : "f"(r3), "f"(r2));
        int col = q * 32 + j * 4;
        uint32_t o = (uint32_t)(row * SA_STR + col) * 2;
        *reinterpret_cast<uint32_t*>(smem + offAH + o)     = h01;
        *reinterpret_cast<uint32_t*>(smem + offAH + o + 4) = h23;
        *reinterpret_cast<uint32_t*>(smem + offAL + o)     = l01;
        *reinterpret_cast<uint32_t*>(smem + offAL + o + 4) = l23;
    }
}

template<int N>
__device__ __forceinline__ void tile_compute_store(uint32_t sbase, int wm, int wn,
                                                   int lane, int row0, int M,
                                                   float* __restrict__ C) {
    constexpr int SA_STR = 136;
    constexpr int SB_STR = N + 8;
    constexpr int OFF_AH = 0;
    constexpr int OFF_AL = OFF_AH + 64 * SA_STR * 2;
    constexpr int OFF_BH = OFF_AL + 64 * SA_STR * 2;
    constexpr int OFF_BL = OFF_BH + 128 * SB_STR * 2;
    constexpr int WN     = N / 4;
    constexpr int NF     = WN / 8;

    float acc[2][NF][4];
    #pragma unroll
    for (int mi = 0; mi < 2; mi++)
        #pragma unroll
        for (int ni = 0; ni < NF; ni++)
            #pragma unroll
            for (int j = 0; j < 4; j++) acc[mi][ni][j] = 0.f;

    const int lrow = lane & 15;
    const int lcol = (lane >> 4) * 8;
    const uint32_t b_col = (uint32_t)(wn * WN) * 2;

    #pragma unroll
    for (int kk = 0; kk < 8; kk++) {
        uint32_t bh[NF][2], bl[NF][2];
        #pragma unroll
        for (int ni = 0; ni < NF; ni++) {
            uint32_t rowoff = (uint32_t)(kk * 16 + lrow) * (SB_STR * 2)
                            + b_col + (uint32_t)ni * 16;
            LDSM_X2T(bh[ni][0], bh[ni][1], sbase + OFF_BH + rowoff);
            LDSM_X2T(bl[ni][0], bl[ni][1], sbase + OFF_BL + rowoff);
        }
        #pragma unroll
        for (int mi = 0; mi < 2; mi++) {
            uint32_t arow = (uint32_t)(wm * 32 + mi * 16 + lrow) * (SA_STR * 2)
                          + (uint32_t)(kk * 16 + lcol) * 2;
            uint32_t ah0, ah1, ah2, ah3, al0, al1, al2, al3;
            LDSM_X4(ah0, ah1, ah2, ah3, sbase + OFF_AH + arow);
            LDSM_X4(al0, al1, al2, al3, sbase + OFF_AL + arow);
            #pragma unroll
            for (int ni = 0; ni < NF; ni++) {
                MMA16816(acc[mi][ni], ah0, ah1, ah2, ah3, bh[ni][0], bh[ni][1]);
                MMA16816(acc[mi][ni], al0, al1, al2, al3, bh[ni][0], bh[ni][1]);
                MMA16816(acc[mi][ni], ah0, ah1, ah2, ah3, bl[ni][0], bl[ni][1]);
            }
        }
    }

    const int g = lane >> 2;
    const int t = lane & 3;
    #pragma unroll
    for (int mi = 0; mi < 2; mi++) {
        int r_hi = row0 + wm * 32 + mi * 16 + g;
        #pragma unroll
        for (int half = 0; half < 2; half++) {
            int r = r_hi + half * 8;
            if (r < M) {
                float* dst = C + (size_t)r * N + wn * WN + t * 2;
                #pragma unroll
                for (int ni = 0; ni < NF; ni++) {
                    float2 o = half ? make_float2(acc[mi][ni][2], acc[mi][ni][3])
                                    : make_float2(acc[mi][ni][0], acc[mi][ni][1]);
                    *reinterpret_cast<float2*>(dst + ni * 8) = o;
                }
            }
        }
    }
}

// ---------------- persistent tensor-core GEMM -----------------------------
// copies B once per CTA, then loops over 64-row tiles with A prefetch
template<int N>
__global__ void __launch_bounds__(256)
mma_gemm(const float* __restrict__ A0, const float* __restrict__ A1,
         const __nv_bfloat16* __restrict__ imgBh0, const __nv_bfloat16* __restrict__ imgBl0,
         const __nv_bfloat16* __restrict__ imgBh1, const __nv_bfloat16* __restrict__ imgBl1,
         float* __restrict__ C0, float* __restrict__ C1, int M) {
    constexpr int SA_STR = 136;
    constexpr int SB_STR = N + 8;
    constexpr int OFF_AH = 0;
    constexpr int OFF_AL = OFF_AH + 64 * SA_STR * 2;
    constexpr int OFF_BH = OFF_AL + 64 * SA_STR * 2;
    constexpr int BCNT   = 128 * SB_STR * 2 / 16;

    extern __shared__ __align__(16) char smem[];
    const uint32_t sbase = smem_u32(smem);

    const int tid  = threadIdx.x;
    const int wid  = tid >> 5;
    const int lane = tid & 31;
    const int wm   = wid >> 2;
    const int wn   = wid & 3;

    const float* A = blockIdx.y ? A1 : A0;
    const __nv_bfloat16* imgBh = blockIdx.y ? imgBh1 : imgBh0;
    const __nv_bfloat16* imgBl = blockIdx.y ? imgBl1 : imgBl0;
    float* C = blockIdx.y ? C1 : C0;

    // B images once per CTA
    {
        const int4* sh = reinterpret_cast<const int4*>(imgBh);
        const int4* sl = reinterpret_cast<const int4*>(imgBl);
        int4* dh = reinterpret_cast<int4*>(smem + OFF_BH);
        int4* dl = reinterpret_cast<int4*>(smem + OFF_BH + 128 * SB_STR * 2);
        #pragma unroll
        for (int i = tid; i < BCNT; i += 256) { dh[i] = sh[i]; dl[i] = sl[i]; }
    }

    const int nTiles = (M + 63) / 64;
    float4 av[8];
    int tile = blockIdx.x;
    if (tile < nTiles) load_A_regs(A, tile * 64, tid, M, av);

    for (; tile < nTiles; tile += gridDim.x) {
        __syncthreads();   // B ready (first) / previous compute finished reading A
        sts_A(smem, OFF_AH, OFF_AL, tid, av);
        __syncthreads();
        int nt = tile + gridDim.x;
        if (nt < nTiles) load_A_regs(A, nt * 64, tid, M, av);
        tile_compute_store<N>(sbase, wm, wn, lane, tile * 64, M, C);
    }
}

// ---------------- host side ----------------
extern "C" void kernel_launch(void* const* d_in, const int* in_sizes, int n_in,
                              void* d_out, int out_size) {
    (void)in_sizes; (void)n_in; (void)out_size;

    const int*   q_rel     = (const int*)  d_in[1];
    const int*   q_tau     = (const int*)  d_in[2];
    const float* hidden    = (const float*)d_in[3];
    const int*   edges     = (const int*)  d_in[4];
    const float* rela      = (const float*)d_in[7];
    const float* Ws        = (const float*)d_in[8];
    const float* Wr        = (const float*)d_in[9];
    const float* Wqr       = (const float*)d_in[10];
    const float* Wqr_b     = (const float*)d_in[11];
    const float* Wtau      = (const float*)d_in[12];
    const float* w_alpha   = (const float*)d_in[13];
    const float* w_alpha_b = (const float*)d_in[14];
    const float* W_h       = (const float*)d_in[15];
    const float* W_h_s     = (const float*)d_in[16];
    const float* w_t1      = (const float*)d_in[17];
    const float* b_t1      = (const float*)d_in[18];
    const float* w_t2      = (const float*)d_in[19];
    const float* b_t2      = (const float*)d_in[20];
    float* out = (float*)d_out;

    void *p_hsW, *p_agg, *p_agg_s, *p_counts;
    void *p_WhH, *p_WhL, *p_WhsH, *p_WhsL, *p_WsH, *p_WsL;
    cudaGetSymbolAddress(&p_hsW,    d_hsW);
    cudaGetSymbolAddress(&p_agg,    d_agg);
    cudaGetSymbolAddress(&p_agg_s,  d_agg_s);
    cudaGetSymbolAddress(&p_counts, d_counts);
    cudaGetSymbolAddress(&p_WhH,  d_Wh_hi);
    cudaGetSymbolAddress(&p_WhL,  d_Wh_lo);
    cudaGetSymbolAddress(&p_WhsH, d_Whs_hi);
    cudaGetSymbolAddress(&p_WhsL, d_Whs_lo);
    cudaGetSymbolAddress(&p_WsH,  d_Ws_hi);
    cudaGetSymbolAddress(&p_WsL,  d_Ws_lo);

    const int SMEM128 = 34816 + 2 * 128 * 136 * 2;  // 104448
    const int SMEM64  = 34816 + 2 * 128 * 72 * 2;   //  71680
    cudaFuncSetAttribute(mma_gemm<128>, cudaFuncAttributeMaxDynamicSharedMemorySize, SMEM128);
    cudaFuncSetAttribute(mma_gemm<64>,  cudaFuncAttributeMaxDynamicSharedMemorySize, SMEM64);

    // ---- counting sort of edges by obj ----
    cudaMemsetAsync(p_counts, 0, N_NODE * sizeof(int));
    hist_kernel<<<(N_EDGE + 255) / 256, 256>>>(edges);
    scan1_kernel<<<N_SCANB, SCAN_B>>>();
    scan3_kernel<<<N_SCANB, SCAN_B>>>();
    fill_kernel<<<(N_EDGE + 255) / 256, 256>>>(edges, q_tau);

    // ---- small tables + weight images ----
    table_kernel<<<N_RELTAB + N_Q + N_TAU, 128>>>(rela, q_rel, q_tau, Wr, Wqr, Wqr_b,
                                                  Wtau, w_t1, b_t1, w_t2, b_t2);
    wprep_kernel<<<128, 136>>>(W_h, W_h_s, Ws);

    // ---- hsW = hidden @ Ws (persistent, 2 CTAs/SM) ----
    mma_gemm<64><<<dim3(296, 1), 256, SMEM64>>>(
        hidden, nullptr,
        (const __nv_bfloat16*)p_WsH, (const __nv_bfloat16*)p_WsL,
        nullptr, nullptr,
        (float*)p_hsW, nullptr, N_NODE);

    // ---- fused alpha + aggregation ----
    agg_kernel<<<(N_NODE * 32 + 255) / 256, 256>>>(hidden, rela, w_alpha, w_alpha_b);

    // ---- output GEMMs (persistent, 2 CTAs/SM across y) ----
    mma_gemm<128><<<dim3(148, 2), 256, SMEM128>>>(
        (const float*)p_agg, (const float*)p_agg_s,
        (const __nv_bfloat16*)p_WhH, (const __nv_bfloat16*)p_WhL,
        (const __nv_bfloat16*)p_WhsH, (const __nv_bfloat16*)p_WhsL,
        out, out + N_NODE * OUT_DIM, N_NODE);
}

// round 10
// speedup vs baseline: 1.3402x; 1.3402x over previous
#include <cuda_runtime.h>
#include <cuda_bf16.h>
#include <math.h>
#include <stdint.h>

#define N_NODE   100000
#define N_EDGE   500000
#define IN_DIM   128
#define OUT_DIM  128
#define ATTN_DIM 64
#define N_RELTAB 401
#define N_Q      64
#define N_TAU    366
#define SCAN_B   1024
#define N_SCANB  ((N_NODE + SCAN_B - 1) / SCAN_B)   // 98

// ---------------- scratch (no allocs allowed) ----------------
__device__ float d_hsW[N_NODE * ATTN_DIM];
__device__ float d_hrW[N_RELTAB * ATTN_DIM];
__device__ float d_qW[N_Q * ATTN_DIM];
__device__ float d_tauW[N_TAU * ATTN_DIM];
__device__ float d_tauTab[N_TAU * IN_DIM];
__device__ float d_agg[N_NODE * IN_DIM];
__device__ float d_agg_s[N_NODE * IN_DIM];

// sort-by-obj machinery
__device__ int d_counts[N_NODE];
__device__ int d_offsets[N_NODE];
__device__ int d_cursor[N_NODE];
__device__ int d_blockSums[N_SCANB + 2];
__device__ int d_pos[N_EDGE];
__device__ int4 d_edat[N_EDGE];          // sorted {sub, rel, t, alpha_bits}

// pre-converted bf16 hi/lo weight images, padded to SMEM stride
__device__ __nv_bfloat16 d_Wh_hi[128 * 136];
__device__ __nv_bfloat16 d_Wh_lo[128 * 136];
__device__ __nv_bfloat16 d_Whs_hi[128 * 136];
__device__ __nv_bfloat16 d_Whs_lo[128 * 136];
__device__ __nv_bfloat16 d_Ws_hi[128 * 72];
__device__ __nv_bfloat16 d_Ws_lo[128 * 72];

// ---------------- helpers ----------------
__device__ __forceinline__ uint32_t smem_u32(const void* p) {
    uint32_t a;
    asm("{ .reg .u64 t; cvta.to.shared.u64 t, %1; cvt.u32.u64 %0, t; }" : "=r"(a) : "l"(p));
    return a;
}

#define LDSM_X4(r0, r1, r2, r3, addr) \
    asm volatile("ldmatrix.sync.aligned.m8n8.x4.shared.b16 {%0,%1,%2,%3}, [%4];" \
                 : "=r"(r0), "=r"(r1), "=r"(r2), "=r"(r3) : "r"(addr))
#define LDSM_X2T(r0, r1, addr) \
    asm volatile("ldmatrix.sync.aligned.m8n8.x2.trans.shared.b16 {%0,%1}, [%2];" \
                 : "=r"(r0), "=r"(r1) : "r"(addr))
#define MMA16816(c, a0, a1, a2, a3, b0, b1) \
    asm volatile("mma.sync.aligned.m16n8k16.row.col.f32.bf16.bf16.f32 " \
                 "{%0,%1,%2,%3}, {%4,%5,%6,%7}, {%8,%9}, {%0,%1,%2,%3};" \
                 : "+f"((c)[0]), "+f"((c)[1]), "+f"((c)[2]), "+f"((c)[3]) \
                 : "r"(a0), "r"(a1), "r"(a2), "r"(a3), "r"(b0), "r"(b1))

// ---------------- build the small tables ----------------
__global__ void table_kernel(const float* __restrict__ rela,
                             const int*   __restrict__ q_rel,
                             const int*   __restrict__ q_tau_p,
                             const float* __restrict__ Wr,
                             const float* __restrict__ Wqr,
                             const float* __restrict__ Wqr_b,
                             const float* __restrict__ Wtau,
                             const float* __restrict__ w_t1,
                             const float* __restrict__ b_t1,
                             const float* __restrict__ w_t2,
                             const float* __restrict__ b_t2) {
    __shared__ float s[IN_DIM];
    int b   = blockIdx.x;
    int tid = threadIdx.x;

    const float* W = nullptr;
    float* outrow  = nullptr;
    bool  add_bias = false;

    if (b < N_RELTAB) {
        s[tid] = rela[(size_t)b * IN_DIM + tid];
        W = Wr; outrow = d_hrW + b * ATTN_DIM;
    } else if (b < N_RELTAB + N_Q) {
        int r = b - N_RELTAB;
        s[tid] = rela[(size_t)q_rel[r] * IN_DIM + tid];
        W = Wqr; outrow = d_qW + r * ATTN_DIM; add_bias = true;
    } else {
        int t = b - N_RELTAB - N_Q;
        float delta = (float)(t - *q_tau_p);
        float v = w_t1[tid] * delta + b_t1[tid] + sinf(w_t2[tid] * delta + b_t2[tid]);
        s[tid] = v;
        d_tauTab[(size_t)t * IN_DIM + tid] = v;
        W = Wtau; outrow = d_tauW + t * ATTN_DIM;
    }
    __syncthreads();

    if (tid < ATTN_DIM) {
        float acc = add_bias ? Wqr_b[tid] : 0.f;
        #pragma unroll 8
        for (int k = 0; k < IN_DIM; k++)
            acc = fmaf(s[k], W[k * ATTN_DIM + tid], acc);
        outrow[tid] = acc;
    }
}

// ---------------- weight prep ----------------
__global__ void wprep_kernel(const float* __restrict__ Wh,
                             const float* __restrict__ Whs,
                             const float* __restrict__ Ws) {
    int k = blockIdx.x;
    int t = threadIdx.x;

    float w1 = (t < 128) ? Wh[k * 128 + t]  : 0.f;
    __nv_bfloat16 h1 = __float2bfloat16(w1);
    d_Wh_hi[k * 136 + t] = h1;
    d_Wh_lo[k * 136 + t] = __float2bfloat16(w1 - __bfloat162float(h1));

    float w2 = (t < 128) ? Whs[k * 128 + t] : 0.f;
    __nv_bfloat16 h2 = __float2bfloat16(w2);
    d_Whs_hi[k * 136 + t] = h2;
    d_Whs_lo[k * 136 + t] = __float2bfloat16(w2 - __bfloat162float(h2));

    if (t < 72) {
        float w3 = (t < 64) ? Ws[k * 64 + t] : 0.f;
        __nv_bfloat16 h3 = __float2bfloat16(w3);
        d_Ws_hi[k * 72 + t] = h3;
        d_Ws_lo[k * 72 + t] = __float2bfloat16(w3 - __bfloat162float(h3));
    }
}

// ---------------- counting sort of edges by obj ----------------
__global__ void hist_kernel(const int* __restrict__ edges) {
    int i = blockIdx.x * blockDim.x + threadIdx.x;
    if (i < N_EDGE) atomicAdd(&d_counts[edges[(size_t)i * 7 + 6]], 1);
}
__global__ void scan1_kernel() {
    __shared__ int sh[SCAN_B];
    int gid = blockIdx.x * SCAN_B + threadIdx.x;
    int v = (gid < N_NODE) ? d_counts[gid] : 0;
    sh[threadIdx.x] = v;
    __syncthreads();
    #pragma unroll
    for (int off = 1; off < SCAN_B; off <<= 1) {
        int t = (threadIdx.x >= off) ? sh[threadIdx.x - off] : 0;
        __syncthreads();
        sh[threadIdx.x] += t;
        __syncthreads();
    }
    if (gid < N_NODE) d_offsets[gid] = sh[threadIdx.x] - v;
    if (threadIdx.x == SCAN_B - 1) d_blockSums[blockIdx.x] = sh[SCAN_B - 1];
}
// fused: each block computes its own block-prefix from raw block sums
__global__ void scan3_kernel() {
    __shared__ int bpref;
    if (threadIdx.x < 32) {
        int s = 0;
        for (int j = threadIdx.x; j < blockIdx.x; j += 32) s += d_blockSums[j];
        #pragma unroll
        for (int o = 16; o; o >>= 1) s += __shfl_xor_sync(0xffffffffu, s, o);
        if (threadIdx.x == 0) bpref = s;
    }
    __syncthreads();
    int gid = blockIdx.x * SCAN_B + threadIdx.x;
    if (gid < N_NODE) {
        int o = d_offsets[gid] + bpref;
        d_offsets[gid] = o;
        d_cursor[gid]  = o;
    }
}
__global__ void fill_kernel(const int* __restrict__ edges) {
    int i = blockIdx.x * blockDim.x + threadIdx.x;
    if (i < N_EDGE) {
        int obj = edges[(size_t)i * 7 + 6];
        d_pos[i] = atomicAdd(&d_cursor[obj], 1);
    }
}

// ---------------- alpha kernel: writes record to SORTED slot ------------
__global__ void alpha_kernel(const int*   __restrict__ edges,
                             const float* __restrict__ w_alpha,
                             const float* __restrict__ w_alpha_b,
                             const int*   __restrict__ q_tau_p) {
    int pw   = (blockIdx.x * blockDim.x + threadIdx.x) >> 5;
    int lane = threadIdx.x & 31;
    int eid  = pw * 2 + (lane >> 4);
    if (eid >= N_EDGE) return;
    int l = lane & 15;

    const int* e = edges + (size_t)eid * 7;
    int r_idx = e[0];
    int rel   = e[2];
    int tau   = e[4];
    int sub   = e[5];
    int t = (tau >= 0) ? tau : *q_tau_p;

    float4 hv = *reinterpret_cast<const float4*>(d_hsW + (size_t)sub * ATTN_DIM + l * 4);
    float4 rv = *reinterpret_cast<const float4*>(d_hrW + rel   * ATTN_DIM + l * 4);
    float4 qv = *reinterpret_cast<const float4*>(d_qW  + r_idx * ATTN_DIM + l * 4);
    float4 tv = *reinterpret_cast<const float4*>(d_tauW + t    * ATTN_DIM + l * 4);
    float4 wa = *reinterpret_cast<const float4*>(w_alpha + l * 4);

    float s = fmaxf(hv.x + rv.x + qv.x + tv.x, 0.f) * wa.x
            + fmaxf(hv.y + rv.y + qv.y + tv.y, 0.f) * wa.y
            + fmaxf(hv.z + rv.z + qv.z + tv.z, 0.f) * wa.z
            + fmaxf(hv.w + rv.w + qv.w + tv.w, 0.f) * wa.w;
    #pragma unroll
    for (int o = 8; o; o >>= 1) s += __shfl_xor_sync(0xffffffffu, s, o);
    if (l == 0) {
        float al = 1.f / (1.f + expf(-(s + w_alpha_b[0])));
        d_edat[d_pos[eid]] = make_int4(sub, rel, t, __float_as_int(al));
    }
}

// ---------------- aggregation: one warp per node, 2-way unrolled ---------
__global__ void __launch_bounds__(256)
agg_kernel(const float* __restrict__ hidden,
           const float* __restrict__ rela) {
    int node = (blockIdx.x * blockDim.x + threadIdx.x) >> 5;
    int lane = threadIdx.x & 31;
    if (node >= N_NODE) return;

    int start = d_offsets[node];
    int cnt   = d_counts[node];

    float4 a1 = make_float4(0.f, 0.f, 0.f, 0.f);
    float4 a2 = make_float4(0.f, 0.f, 0.f, 0.f);

    int i = 0;
    for (; i + 2 <= cnt; i += 2) {
        int4 e0 = __ldg(&d_edat[start + i]);
        int4 e1 = __ldg(&d_edat[start + i + 1]);
        float av0 = __int_as_float(e0.w);
        float av1 = __int_as_float(e1.w);

        float4 hs0 = *reinterpret_cast<const float4*>(hidden + (size_t)e0.x * IN_DIM + lane * 4);
        float4 hs1 = *reinterpret_cast<const float4*>(hidden + (size_t)e1.x * IN_DIM + lane * 4);
        float4 hr0 = *reinterpret_cast<const float4*>(rela   + (size_t)e0.y * IN_DIM + lane * 4);
        float4 hr1 = *reinterpret_cast<const float4*>(rela   + (size_t)e1.y * IN_DIM + lane * 4);
        float4 ht0 = *reinterpret_cast<const float4*>(d_tauTab + (size_t)e0.z * IN_DIM + lane * 4);
        float4 ht1 = *reinterpret_cast<const float4*>(d_tauTab + (size_t)e1.z * IN_DIM + lane * 4);

        float mx0 = hs0.x + hr0.x + ht0.x, my0 = hs0.y + hr0.y + ht0.y;
        float mz0 = hs0.z + hr0.z + ht0.z, mw0 = hs0.w + hr0.w + ht0.w;
        float mx1 = hs1.x + hr1.x + ht1.x, my1 = hs1.y + hr1.y + ht1.y;
        float mz1 = hs1.z + hr1.z + ht1.z, mw1 = hs1.w + hr1.w + ht1.w;

        a1.x = fmaf(av0, mx0, fmaf(av1, mx1, a1.x));
        a1.y = fmaf(av0, my0, fmaf(av1, my1, a1.y));
        a1.z = fmaf(av0, mz0, fmaf(av1, mz1, a1.z));
        a1.w = fmaf(av0, mw0, fmaf(av1, mw1, a1.w));
        a2.x += (mx0 - av0 * mx0) + (mx1 - av1 * mx1);
        a2.y += (my0 - av0 * my0) + (my1 - av1 * my1);
        a2.z += (mz0 - av0 * mz0) + (mz1 - av1 * mz1);
        a2.w += (mw0 - av0 * mw0) + (mw1 - av1 * mw1);
    }
    if (i < cnt) {
        int4 e0 = __ldg(&d_edat[start + i]);
        float av0 = __int_as_float(e0.w);
        float4 hs0 = *reinterpret_cast<const float4*>(hidden + (size_t)e0.x * IN_DIM + lane * 4);
        float4 hr0 = *reinterpret_cast<const float4*>(rela   + (size_t)e0.y * IN_DIM + lane * 4);
        float4 ht0 = *reinterpret_cast<const float4*>(d_tauTab + (size_t)e0.z * IN_DIM + lane * 4);
        float mx0 = hs0.x + hr0.x + ht0.x, my0 = hs0.y + hr0.y + ht0.y;
        float mz0 = hs0.z + hr0.z + ht0.z, mw0 = hs0.w + hr0.w + ht0.w;
        a1.x = fmaf(av0, mx0, a1.x); a1.y = fmaf(av0, my0, a1.y);
        a1.z = fmaf(av0, mz0, a1.z); a1.w = fmaf(av0, mw0, a1.w);
        a2.x += mx0 - av0 * mx0; a2.y += my0 - av0 * my0;
        a2.z += mz0 - av0 * mz0; a2.w += mw0 - av0 * mw0;
    }

    *reinterpret_cast<float4*>(d_agg   + (size_t)node * IN_DIM + lane * 4) = a1;
    *reinterpret_cast<float4*>(d_agg_s + (size_t)node * IN_DIM + lane * 4) = a2;
}

// ---------------- GEMM tile helpers ----------------
__device__ __forceinline__ void load_A_regs(const float* __restrict__ A, int row0,
                                            int tid, int M, float4* v) {
    int row  = tid >> 2;
    int q    = tid & 3;
    int grow = row0 + row;
    bool valid = grow < M;
    const float4* src = reinterpret_cast<const float4*>(A + (size_t)grow * 128 + q * 32);
    #pragma unroll
    for (int j = 0; j < 8; j++)
        v[j] = valid ? src[j] : make_float4(0.f, 0.f, 0.f, 0.f);
}

__device__ __forceinline__ void sts_A(char* smem, int offAH, int offAL,
                                      int tid, const float4* v) {
    constexpr int SA_STR = 136;
    int row = tid >> 2;
    int q   = tid & 3;
    #pragma unroll
    for (int j = 0; j < 8; j++) {
        float4 x = v[j];
        uint32_t h01, h23, l01, l23;
        asm("cvt.rn.bf16x2.f32 %0, %1, %2;" : "=r"(h01) : "f"(x.y), "f"(x.x));
        asm("cvt.rn.bf16x2.f32 %0, %1, %2;" : "=r"(h23) : "f"(x.w), "f"(x.z));
        float r0 = x.x - __uint_as_float(h01 << 16);
        float r1 = x.y - __uint_as_float(h01 & 0xffff0000u);
        float r2 = x.z - __uint_as_float(h23 << 16);
        float r3 = x.w - __uint_as_float(h23 & 0xffff0000u);
        asm("cvt.rn.bf16x2.f32 %0, %1, %2;" : "=r"(l01) : "f"(r1), "f"(r0));
        asm("cvt.rn.bf16x2.f32 %0, %1, %2;" : "=r"(l23) : "f"(r3), "f"(r2));
        int col = q * 32 + j * 4;
        uint32_t o = (uint32_t)(row * SA_STR + col) * 2;
        *reinterpret_cast<uint32_t*>(smem + offAH + o)     = h01;
        *reinterpret_cast<uint32_t*>(smem + offAH + o + 4) = h23;
        *reinterpret_cast<uint32_t*>(smem + offAL + o)     = l01;
        *reinterpret_cast<uint32_t*>(smem + offAL + o + 4) = l23;
    }
}

template<int N>
__device__ __forceinline__ void tile_compute_store(uint32_t sbase, int wm, int wn,
                                                   int lane, int row0, int M,
                                                   float* __restrict__ C) {
    constexpr int SA_STR = 136;
    constexpr int SB_STR = N + 8;
    constexpr int OFF_AH = 0;
    constexpr int OFF_AL = OFF_AH + 64 * SA_STR * 2;
    constexpr int OFF_BH = OFF_AL + 64 * SA_STR * 2;
    constexpr int OFF_BL = OFF_BH + 128 * SB_STR * 2;
    constexpr int WN     = N / 4;
    constexpr int NF     = WN / 8;

    float acc[2][NF][4];
    #pragma unroll
    for (int mi = 0; mi < 2; mi++)
        #pragma unroll
        for (int ni = 0; ni < NF; ni++)
            #pragma unroll
            for (int j = 0; j < 4; j++) acc[mi][ni][j] = 0.f;

    const int lrow = lane & 15;
    const int lcol = (lane >> 4) * 8;
    const uint32_t b_col = (uint32_t)(wn * WN) * 2;

    #pragma unroll
    for (int kk = 0; kk < 8; kk++) {
        uint32_t bh[NF][2], bl[NF][2];
        #pragma unroll
        for (int ni = 0; ni < NF; ni++) {
            uint32_t rowoff = (uint32_t)(kk * 16 + lrow) * (SB_STR * 2)
                            + b_col + (uint32_t)ni * 16;
            LDSM_X2T(bh[ni][0], bh[ni][1], sbase + OFF_BH + rowoff);
            LDSM_X2T(bl[ni][0], bl[ni][1], sbase + OFF_BL + rowoff);
        }
        #pragma unroll
        for (int mi = 0; mi < 2; mi++) {
            uint32_t arow = (uint32_t)(wm * 32 + mi * 16 + lrow) * (SA_STR * 2)
                          + (uint32_t)(kk * 16 + lcol) * 2;
            uint32_t ah0, ah1, ah2, ah3, al0, al1, al2, al3;
            LDSM_X4(ah0, ah1, ah2, ah3, sbase + OFF_AH + arow);
            LDSM_X4(al0, al1, al2, al3, sbase + OFF_AL + arow);
            #pragma unroll
            for (int ni = 0; ni < NF; ni++) {
                MMA16816(acc[mi][ni], ah0, ah1, ah2, ah3, bh[ni][0], bh[ni][1]);
                MMA16816(acc[mi][ni], al0, al1, al2, al3, bh[ni][0], bh[ni][1]);
                MMA16816(acc[mi][ni], ah0, ah1, ah2, ah3, bl[ni][0], bl[ni][1]);
            }
        }
    }

    const int g = lane >> 2;
    const int t = lane & 3;
    #pragma unroll
    for (int mi = 0; mi < 2; mi++) {
        int r_hi = row0 + wm * 32 + mi * 16 + g;
        #pragma unroll
        for (int half = 0; half < 2; half++) {
            int r = r_hi + half * 8;
            if (r < M) {
                float* dst = C + (size_t)r * N + wn * WN + t * 2;
                #pragma unroll
                for (int ni = 0; ni < NF; ni++) {
                    float2 o = half ? make_float2(acc[mi][ni][2], acc[mi][ni][3])
                                    : make_float2(acc[mi][ni][0], acc[mi][ni][1]);
                    *reinterpret_cast<float2*>(dst + ni * 8) = o;
                }
            }
        }
    }
}

// ---------------- tensor-core GEMM: 2 tiles (128 rows) per CTA ----------
template<int N>
__global__ void __launch_bounds__(256)
mma_gemm(const float* __restrict__ A0, const float* __restrict__ A1,
         const __nv_bfloat16* __restrict__ imgBh0, const __nv_bfloat16* __restrict__ imgBl0,
         const __nv_bfloat16* __restrict__ imgBh1, const __nv_bfloat16* __restrict__ imgBl1,
         float* __restrict__ C0, float* __restrict__ C1, int M) {
    constexpr int SA_STR = 136;
    constexpr int SB_STR = N + 8;
    constexpr int OFF_AH = 0;
    constexpr int OFF_AL = OFF_AH + 64 * SA_STR * 2;
    constexpr int OFF_BH = OFF_AL + 64 * SA_STR * 2;
    constexpr int BCNT   = 128 * SB_STR * 2 / 16;

    extern __shared__ __align__(16) char smem[];
    const uint32_t sbase = smem_u32(smem);

    const int tid  = threadIdx.x;
    const int wid  = tid >> 5;
    const int lane = tid & 31;
    const int wm   = wid >> 2;
    const int wn   = wid & 3;
    const int row0 = blockIdx.x * 128;
    const int row1 = row0 + 64;

    const float* A = blockIdx.y ? A1 : A0;
    const __nv_bfloat16* imgBh = blockIdx.y ? imgBh1 : imgBh0;
    const __nv_bfloat16* imgBl = blockIdx.y ? imgBl1 : imgBl0;
    float* C = blockIdx.y ? C1 : C0;

    // B images (once per CTA, L2-hot)
    {
        const int4* sh = reinterpret_cast<const int4*>(imgBh);
        const int4* sl = reinterpret_cast<const int4*>(imgBl);
        int4* dh = reinterpret_cast<int4*>(smem + OFF_BH);
        int4* dl = reinterpret_cast<int4*>(smem + OFF_BH + 128 * SB_STR * 2);
        #pragma unroll
        for (int i = tid; i < BCNT; i += 256) { dh[i] = sh[i]; dl[i] = sl[i]; }
    }

    // tile0 A: load + convert + STS
    float4 av[8];
    load_A_regs(A, row0, tid, M, av);
    sts_A(smem, OFF_AH, OFF_AL, tid, av);
    __syncthreads();

    // prefetch tile1 A while tile0 computes
    float4 av1[8];
    load_A_regs(A, row1, tid, M, av1);

    tile_compute_store<N>(sbase, wm, wn, lane, row0, M, C);
    __syncthreads();

    sts_A(smem, OFF_AH, OFF_AL, tid, av1);
    __syncthreads();

    tile_compute_store<N>(sbase, wm, wn, lane, row1, M, C);
}

// ---------------- host side ----------------
extern "C" void kernel_launch(void* const* d_in, const int* in_sizes, int n_in,
                              void* d_out, int out_size) {
    (void)in_sizes; (void)n_in; (void)out_size;

    const int*   q_rel     = (const int*)  d_in[1];
    const int*   q_tau     = (const int*)  d_in[2];
    const float* hidden    = (const float*)d_in[3];
    const int*   edges     = (const int*)  d_in[4];
    const float* rela      = (const float*)d_in[7];
    const float* Ws        = (const float*)d_in[8];
    const float* Wr        = (const float*)d_in[9];
    const float* Wqr       = (const float*)d_in[10];
    const float* Wqr_b     = (const float*)d_in[11];
    const float* Wtau      = (const float*)d_in[12];
    const float* w_alpha   = (const float*)d_in[13];
    const float* w_alpha_b = (const float*)d_in[14];
    const float* W_h       = (const float*)d_in[15];
    const float* W_h_s     = (const float*)d_in[16];
    const float* w_t1      = (const float*)d_in[17];
    const float* b_t1      = (const float*)d_in[18];
    const float* w_t2      = (const float*)d_in[19];
    const float* b_t2      = (const float*)d_in[20];
    float* out = (float*)d_out;

    void *p_hsW, *p_agg, *p_agg_s, *p_counts;
    void *p_WhH, *p_WhL, *p_WhsH, *p_WhsL, *p_WsH, *p_WsL;
    cudaGetSymbolAddress(&p_hsW,    d_hsW);
    cudaGetSymbolAddress(&p_agg,    d_agg);
    cudaGetSymbolAddress(&p_agg_s,  d_agg_s);
    cudaGetSymbolAddress(&p_counts, d_counts);
    cudaGetSymbolAddress(&p_WhH,  d_Wh_hi);
    cudaGetSymbolAddress(&p_WhL,  d_Wh_lo);
    cudaGetSymbolAddress(&p_WhsH, d_Whs_hi);
    cudaGetSymbolAddress(&p_WhsL, d_Whs_lo);
    cudaGetSymbolAddress(&p_WsH,  d_Ws_hi);
    cudaGetSymbolAddress(&p_WsL,  d_Ws_lo);

    const int SMEM128 = 34816 + 2 * 128 * 136 * 2;  // 104448
    const int SMEM64  = 34816 + 2 * 128 * 72 * 2;   //  71680
    cudaFuncSetAttribute(mma_gemm<128>, cudaFuncAttributeMaxDynamicSharedMemorySize, SMEM128);
    cudaFuncSetAttribute(mma_gemm<64>,  cudaFuncAttributeMaxDynamicSharedMemorySize, SMEM64);

    // ---- counting sort of edges by obj ----
    cudaMemsetAsync(p_counts, 0, N_NODE * sizeof(int));
    hist_kernel<<<(N_EDGE + 255) / 256, 256>>>(edges);
    scan1_kernel<<<N_SCANB, SCAN_B>>>();
    scan3_kernel<<<N_SCANB, SCAN_B>>>();
    fill_kernel<<<(N_EDGE + 255) / 256, 256>>>(edges);

    // ---- small tables + weight images ----
    table_kernel<<<N_RELTAB + N_Q + N_TAU, 128>>>(rela, q_rel, q_tau, Wr, Wqr, Wqr_b,
                                                  Wtau, w_t1, b_t1, w_t2, b_t2);
    wprep_kernel<<<128, 136>>>(W_h, W_h_s, Ws);

    int gm2 = (N_NODE + 127) / 128;   // 782 (two 64-row tiles per CTA)
    // ---- hsW = hidden @ Ws ----
    mma_gemm<64><<<dim3(gm2, 1), 256, SMEM64>>>(
        hidden, nullptr,
        (const __nv_bfloat16*)p_WsH, (const __nv_bfloat16*)p_WsL,
        nullptr, nullptr,
        (float*)p_hsW, nullptr, N_NODE);
    // ---- attention alphas -> sorted records ----
    int nwarp = (N_EDGE + 1) / 2;
    int nblk  = (nwarp * 32 + 255) / 256;
    alpha_kernel<<<nblk, 256>>>(edges, w_alpha, w_alpha_b, q_tau);
    // ---- sorted aggregation ----
    agg_kernel<<<(N_NODE * 32 + 255) / 256, 256>>>(hidden, rela);
    // ---- output GEMMs (one launch, blockIdx.y selects pair) ----
    mma_gemm<128><<<dim3(gm2, 2), 256, SMEM128>>>(
        (const float*)p_agg, (const float*)p_agg_s,
        (const __nv_bfloat16*)p_WhH, (const __nv_bfloat16*)p_WhL,
        (const __nv_bfloat16*)p_WhsH, (const __nv_bfloat16*)p_WhsL,
        out, out + N_NODE * OUT_DIM, N_NODE);
}

// round 14
// speedup vs baseline: 1.3617x; 1.0161x over previous
#include <cuda_runtime.h>
#include <cuda_bf16.h>
#include <math.h>
#include <stdint.h>

#define N_NODE   100000
#define N_EDGE   500000
#define IN_DIM   128
#define OUT_DIM  128
#define ATTN_DIM 64
#define N_RELTAB 401
#define N_Q      64
#define N_TAU    366
#define SCAN_B   1024
#define N_SCANB  ((N_NODE + SCAN_B - 1) / SCAN_B)   // 98

// ---------------- scratch (no allocs allowed) ----------------
__device__ float d_hsW[N_NODE * ATTN_DIM];
__device__ float d_hrW[N_RELTAB * ATTN_DIM];
__device__ float d_qW[N_Q * ATTN_DIM];
__device__ float d_tauW[N_TAU * ATTN_DIM];
__device__ float d_tauTab[N_TAU * IN_DIM];
__device__ float d_agg[N_NODE * IN_DIM];
__device__ float d_agg_s[N_NODE * IN_DIM];

// sort-by-obj machinery
__device__ int d_counts[N_NODE];
__device__ int d_offsets[N_NODE];
__device__ int d_cursor[N_NODE];
__device__ int d_blockSums[N_SCANB + 2];
__device__ int d_pos[N_EDGE];
__device__ int4 d_edat[N_EDGE];          // sorted {sub, rel, t, alpha_bits}

// pre-converted bf16 hi/lo weight images, padded to SMEM stride
__device__ __nv_bfloat16 d_Wh_hi[128 * 136];
__device__ __nv_bfloat16 d_Wh_lo[128 * 136];
__device__ __nv_bfloat16 d_Whs_hi[128 * 136];
__device__ __nv_bfloat16 d_Whs_lo[128 * 136];
__device__ __nv_bfloat16 d_Ws_hi[128 * 72];
__device__ __nv_bfloat16 d_Ws_lo[128 * 72];

// ---------------- helpers ----------------
__device__ __forceinline__ uint32_t smem_u32(const void* p) {
    uint32_t a;
    asm("{ .reg .u64 t; cvta.to.shared.u64 t, %1; cvt.u32.u64 %0, t; }" : "=r"(a) : "l"(p));
    return a;
}

#define LDSM_X4(r0, r1, r2, r3, addr) \
    asm volatile("ldmatrix.sync.aligned.m8n8.x4.shared.b16 {%0,%1,%2,%3}, [%4];" \
                 : "=r"(r0), "=r"(r1), "=r"(r2), "=r"(r3) : "r"(addr))
#define LDSM_X2T(r0, r1, addr) \
    asm volatile("ldmatrix.sync.aligned.m8n8.x2.trans.shared.b16 {%0,%1}, [%2];" \
                 : "=r"(r0), "=r"(r1) : "r"(addr))
#define MMA16816(c, a0, a1, a2, a3, b0, b1) \
    asm volatile("mma.sync.aligned.m16n8k16.row.col.f32.bf16.bf16.f32 " \
                 "{%0,%1,%2,%3}, {%4,%5,%6,%7}, {%8,%9}, {%0,%1,%2,%3};" \
                 : "+f"((c)[0]), "+f"((c)[1]), "+f"((c)[2]), "+f"((c)[3]) \
                 : "r"(a0), "r"(a1), "r"(a2), "r"(a3), "r"(b0), "r"(b1))

// ---------------- build the small tables ----------------
__global__ void table_kernel(const float* __restrict__ rela,
                             const int*   __restrict__ q_rel,
                             const int*   __restrict__ q_tau_p,
                             const float* __restrict__ Wr,
                             const float* __restrict__ Wqr,
                             const float* __restrict__ Wqr_b,
                             const float* __restrict__ Wtau,
                             const float* __restrict__ w_t1,
                             const float* __restrict__ b_t1,
                             const float* __restrict__ w_t2,
                             const float* __restrict__ b_t2) {
    __shared__ float s[IN_DIM];
    int b   = blockIdx.x;
    int tid = threadIdx.x;

    const float* W = nullptr;
    float* outrow  = nullptr;
    bool  add_bias = false;

    if (b < N_RELTAB) {
        s[tid] = rela[(size_t)b * IN_DIM + tid];
        W = Wr; outrow = d_hrW + b * ATTN_DIM;
    } else if (b < N_RELTAB + N_Q) {
        int r = b - N_RELTAB;
        s[tid] = rela[(size_t)q_rel[r] * IN_DIM + tid];
        W = Wqr; outrow = d_qW + r * ATTN_DIM; add_bias = true;
    } else {
        int t = b - N_RELTAB - N_Q;
        float delta = (float)(t - *q_tau_p);
        float v = w_t1[tid] * delta + b_t1[tid] + sinf(w_t2[tid] * delta + b_t2[tid]);
        s[tid] = v;
        d_tauTab[(size_t)t * IN_DIM + tid] = v;
        W = Wtau; outrow = d_tauW + t * ATTN_DIM;
    }
    __syncthreads();

    if (tid < ATTN_DIM) {
        float acc = add_bias ? Wqr_b[tid] : 0.f;
        #pragma unroll 8
        for (int k = 0; k < IN_DIM; k++)
            acc = fmaf(s[k], W[k * ATTN_DIM + tid], acc);
        outrow[tid] = acc;
    }
}

// ---------------- weight prep ----------------
__global__ void wprep_kernel(const float* __restrict__ Wh,
                             const float* __restrict__ Whs,
                             const float* __restrict__ Ws) {
    int k = blockIdx.x;
    int t = threadIdx.x;

    float w1 = (t < 128) ? Wh[k * 128 + t]  : 0.f;
    __nv_bfloat16 h1 = __float2bfloat16(w1);
    d_Wh_hi[k * 136 + t] = h1;
    d_Wh_lo[k * 136 + t] = __float2bfloat16(w1 - __bfloat162float(h1));

    float w2 = (t < 128) ? Whs[k * 128 + t] : 0.f;
    __nv_bfloat16 h2 = __float2bfloat16(w2);
    d_Whs_hi[k * 136 + t] = h2;
    d_Whs_lo[k * 136 + t] = __float2bfloat16(w2 - __bfloat162float(h2));

    if (t < 72) {
        float w3 = (t < 64) ? Ws[k * 64 + t] : 0.f;
        __nv_bfloat16 h3 = __float2bfloat16(w3);
        d_Ws_hi[k * 72 + t] = h3;
        d_Ws_lo[k * 72 + t] = __float2bfloat16(w3 - __bfloat162float(h3));
    }
}

// ---------------- counting sort of edges by obj ----------------
__global__ void hist_kernel(const int* __restrict__ edges) {
    int i = blockIdx.x * blockDim.x + threadIdx.x;
    if (i < N_EDGE) atomicAdd(&d_counts[edges[(size_t)i * 7 + 6]], 1);
}
__global__ void scan1_kernel() {
    __shared__ int sh[SCAN_B];
    int gid = blockIdx.x * SCAN_B + threadIdx.x;
    int v = (gid < N_NODE) ? d_counts[gid] : 0;
    sh[threadIdx.x] = v;
    __syncthreads();
    #pragma unroll
    for (int off = 1; off < SCAN_B; off <<= 1) {
        int t = (threadIdx.x >= off) ? sh[threadIdx.x - off] : 0;
        __syncthreads();
        sh[threadIdx.x] += t;
        __syncthreads();
    }
    if (gid < N_NODE) d_offsets[gid] = sh[threadIdx.x] - v;
    if (threadIdx.x == SCAN_B - 1) d_blockSums[blockIdx.x] = sh[SCAN_B - 1];
}
// fused: each block computes its own block-prefix from raw block sums
__global__ void scan3_kernel() {
    __shared__ int bpref;
    if (threadIdx.x < 32) {
        int s = 0;
        for (int j = threadIdx.x; j < blockIdx.x; j += 32) s += d_blockSums[j];
        #pragma unroll
        for (int o = 16; o; o >>= 1) s += __shfl_xor_sync(0xffffffffu, s, o);
        if (threadIdx.x == 0) bpref = s;
    }
    __syncthreads();
    int gid = blockIdx.x * SCAN_B + threadIdx.x;
    if (gid < N_NODE) {
        int o = d_offsets[gid] + bpref;
        d_offsets[gid] = o;
        d_cursor[gid]  = o;
    }
}
__global__ void fill_kernel(const int* __restrict__ edges) {
    int i = blockIdx.x * blockDim.x + threadIdx.x;
    if (i < N_EDGE) {
        int obj = edges[(size_t)i * 7 + 6];
        d_pos[i] = atomicAdd(&d_cursor[obj], 1);
    }
}

// ---------------- alpha kernel: writes record to SORTED slot ------------
__global__ void alpha_kernel(const int*   __restrict__ edges,
                             const float* __restrict__ w_alpha,
                             const float* __restrict__ w_alpha_b,
                             const int*   __restrict__ q_tau_p) {
    int pw   = (blockIdx.x * blockDim.x + threadIdx.x) >> 5;
    int lane = threadIdx.x & 31;
    int eid  = pw * 2 + (lane >> 4);
    if (eid >= N_EDGE) return;
    int l = lane & 15;

    const int* e = edges + (size_t)eid * 7;
    int r_idx = e[0];
    int rel   = e[2];
    int tau   = e[4];
    int sub   = e[5];
    int t = (tau >= 0) ? tau : *q_tau_p;

    float4 hv = *reinterpret_cast<const float4*>(d_hsW + (size_t)sub * ATTN_DIM + l * 4);
    float4 rv = *reinterpret_cast<const float4*>(d_hrW + rel   * ATTN_DIM + l * 4);
    float4 qv = *reinterpret_cast<const float4*>(d_qW  + r_idx * ATTN_DIM + l * 4);
    float4 tv = *reinterpret_cast<const float4*>(d_tauW + t    * ATTN_DIM + l * 4);
    float4 wa = *reinterpret_cast<const float4*>(w_alpha + l * 4);

    float s = fmaxf(hv.x + rv.x + qv.x + tv.x, 0.f) * wa.x
            + fmaxf(hv.y + rv.y + qv.y + tv.y, 0.f) * wa.y
            + fmaxf(hv.z + rv.z + qv.z + tv.z, 0.f) * wa.z
            + fmaxf(hv.w + rv.w + qv.w + tv.w, 0.f) * wa.w;
    #pragma unroll
    for (int o = 8; o; o >>= 1) s += __shfl_xor_sync(0xffffffffu, s, o);
    if (l == 0) {
        float al = 1.f / (1.f + expf(-(s + w_alpha_b[0])));
        d_edat[d_pos[eid]] = make_int4(sub, rel, t, __float_as_int(al));
    }
}

// ---------------- aggregation: one warp per node, 2-way unrolled ---------
__global__ void __launch_bounds__(256)
agg_kernel(const float* __restrict__ hidden,
           const float* __restrict__ rela) {
    int node = (blockIdx.x * blockDim.x + threadIdx.x) >> 5;
    int lane = threadIdx.x & 31;
    if (node >= N_NODE) return;

    int start = d_offsets[node];
    int cnt   = d_counts[node];

    float4 a1 = make_float4(0.f, 0.f, 0.f, 0.f);
    float4 a2 = make_float4(0.f, 0.f, 0.f, 0.f);

    int i = 0;
    for (; i + 2 <= cnt; i += 2) {
        int4 e0 = __ldg(&d_edat[start + i]);
        int4 e1 = __ldg(&d_edat[start + i + 1]);
        float av0 = __int_as_float(e0.w);
        float av1 = __int_as_float(e1.w);

        float4 hs0 = *reinterpret_cast<const float4*>(hidden + (size_t)e0.x * IN_DIM + lane * 4);
        float4 hs1 = *reinterpret_cast<const float4*>(hidden + (size_t)e1.x * IN_DIM + lane * 4);
        float4 hr0 = *reinterpret_cast<const float4*>(rela   + (size_t)e0.y * IN_DIM + lane * 4);
        float4 hr1 = *reinterpret_cast<const float4*>(rela   + (size_t)e1.y * IN_DIM + lane * 4);
        float4 ht0 = *reinterpret_cast<const float4*>(d_tauTab + (size_t)e0.z * IN_DIM + lane * 4);
        float4 ht1 = *reinterpret_cast<const float4*>(d_tauTab + (size_t)e1.z * IN_DIM + lane * 4);

        float mx0 = hs0.x + hr0.x + ht0.x, my0 = hs0.y + hr0.y + ht0.y;
        float mz0 = hs0.z + hr0.z + ht0.z, mw0 = hs0.w + hr0.w + ht0.w;
        float mx1 = hs1.x + hr1.x + ht1.x, my1 = hs1.y + hr1.y + ht1.y;
        float mz1 = hs1.z + hr1.z + ht1.z, mw1 = hs1.w + hr1.w + ht1.w;

        a1.x = fmaf(av0, mx0, fmaf(av1, mx1, a1.x));
        a1.y = fmaf(av0, my0, fmaf(av1, my1, a1.y));
        a1.z = fmaf(av0, mz0, fmaf(av1, mz1, a1.z));
        a1.w = fmaf(av0, mw0, fmaf(av1, mw1, a1.w));
        a2.x += (mx0 - av0 * mx0) + (mx1 - av1 * mx1);
        a2.y += (my0 - av0 * my0) + (my1 - av1 * my1);
        a2.z += (mz0 - av0 * mz0) + (mz1 - av1 * mz1);
        a2.w += (mw0 - av0 * mw0) + (mw1 - av1 * mw1);
    }
    if (i < cnt) {
        int4 e0 = __ldg(&d_edat[start + i]);
        float av0 = __int_as_float(e0.w);
        float4 hs0 = *reinterpret_cast<const float4*>(hidden + (size_t)e0.x * IN_DIM + lane * 4);
        float4 hr0 = *reinterpret_cast<const float4*>(rela   + (size_t)e0.y * IN_DIM + lane * 4);
        float4 ht0 = *reinterpret_cast<const float4*>(d_tauTab + (size_t)e0.z * IN_DIM + lane * 4);
        float mx0 = hs0.x + hr0.x + ht0.x, my0 = hs0.y + hr0.y + ht0.y;
        float mz0 = hs0.z + hr0.z + ht0.z, mw0 = hs0.w + hr0.w + ht0.w;
        a1.x = fmaf(av0, mx0, a1.x); a1.y = fmaf(av0, my0, a1.y);
        a1.z = fmaf(av0, mz0, a1.z); a1.w = fmaf(av0, mw0, a1.w);
        a2.x += mx0 - av0 * mx0; a2.y += my0 - av0 * my0;
        a2.z += mz0 - av0 * mz0; a2.w += mw0 - av0 * mw0;
    }

    *reinterpret_cast<float4*>(d_agg   + (size_t)node * IN_DIM + lane * 4) = a1;
    *reinterpret_cast<float4*>(d_agg_s + (size_t)node * IN_DIM + lane * 4) = a2;
}

// ---------------- GEMM tile helpers ----------------
__device__ __forceinline__ void load_A_regs(const float* __restrict__ A, int row0,
                                            int tid, int M, float4* v) {
    int row  = tid >> 2;
    int q    = tid & 3;
    int grow = row0 + row;
    bool valid = grow < M;
    const float4* src = reinterpret_cast<const float4*>(A + (size_t)grow * 128 + q * 32);
    #pragma unroll
    for (int j = 0; j < 8; j++)
        v[j] = valid ? src[j] : make_float4(0.f, 0.f, 0.f, 0.f);
}

__device__ __forceinline__ void sts_A(char* smem, int offAH, int offAL,
                                      int tid, const float4* v) {
    constexpr int SA_STR = 136;
    int row = tid >> 2;
    int q   = tid & 3;
    #pragma unroll
    for (int j = 0; j < 8; j++) {
        float4 x = v[j];
        uint32_t h01, h23, l01, l23;
        asm("cvt.rn.bf16x2.f32 %0, %1, %2;" : "=r"(h01) : "f"(x.y), "f"(x.x));
        asm("cvt.rn.bf16x2.f32 %0, %1, %2;" : "=r"(h23) : "f"(x.w), "f"(x.z));
        float r0 = x.x - __uint_as_float(h01 << 16);
        float r1 = x.y - __uint_as_float(h01 & 0xffff0000u);
        float r2 = x.z - __uint_as_float(h23 << 16);
        float r3 = x.w - __uint_as_float(h23 & 0xffff0000u);
        asm("cvt.rn.bf16x2.f32 %0, %1, %2;" : "=r"(l01) : "f"(r1), "f"(r0));
        asm("cvt.rn.bf16x2.f32 %0, %1, %2;" : "=r"(l23) : "f"(r3), "f"(r2));
        int col = q * 32 + j * 4;
        uint32_t o = (uint32_t)(row * SA_STR + col) * 2;
        *reinterpret_cast<uint32_t*>(smem + offAH + o)     = h01;
        *reinterpret_cast<uint32_t*>(smem + offAH + o + 4) = h23;
        *reinterpret_cast<uint32_t*>(smem + offAL + o)     = l01;
        *reinterpret_cast<uint32_t*>(smem + offAL + o + 4) = l23;
    }
}

template<int N>
__device__ __forceinline__ void tile_compute_store(uint32_t sbase, int wm, int wn,
                                                   int lane, int row0, int M,
                                                   float* __restrict__ C) {
    constexpr int SA_STR = 136;
    constexpr int SB_STR = N + 8;
    constexpr int OFF_AH = 0;
    constexpr int OFF_AL = OFF_AH + 64 * SA_STR * 2;
    constexpr int OFF_BH = OFF_AL + 64 * SA_STR * 2;
    constexpr int OFF_BL = OFF_BH + 128 * SB_STR * 2;
    constexpr int WN     = N / 4;
    constexpr int NF     = WN / 8;

    float acc[2][NF][4];
    #pragma unroll
    for (int mi = 0; mi < 2; mi++)
        #pragma unroll
        for (int ni = 0; ni < NF; ni++)
            #pragma unroll
            for (int j = 0; j < 4; j++) acc[mi][ni][j] = 0.f;

    const int lrow = lane & 15;
    const int lcol = (lane >> 4) * 8;
    const uint32_t b_col = (uint32_t)(wn * WN) * 2;

    #pragma unroll
    for (int kk = 0; kk < 8; kk++) {
        uint32_t bh[NF][2], bl[NF][2];
        #pragma unroll
        for (int ni = 0; ni < NF; ni++) {
            uint32_t rowoff = (uint32_t)(kk * 16 + lrow) * (SB_STR * 2)
                            + b_col + (uint32_t)ni * 16;
            LDSM_X2T(bh[ni][0], bh[ni][1], sbase + OFF_BH + rowoff);
            LDSM_X2T(bl[ni][0], bl[ni][1], sbase + OFF_BL + rowoff);
        }
        #pragma unroll
        for (int mi = 0; mi < 2; mi++) {
            uint32_t arow = (uint32_t)(wm * 32 + mi * 16 + lrow) * (SA_STR * 2)
                          + (uint32_t)(kk * 16 + lcol) * 2;
            uint32_t ah0, ah1, ah2, ah3, al0, al1, al2, al3;
            LDSM_X4(ah0, ah1, ah2, ah3, sbase + OFF_AH + arow);
            LDSM_X4(al0, al1, al2, al3, sbase + OFF_AL + arow);
            #pragma unroll
            for (int ni = 0; ni < NF; ni++) {
                MMA16816(acc[mi][ni], ah0, ah1, ah2, ah3, bh[ni][0], bh[ni][1]);
                MMA16816(acc[mi][ni], al0, al1, al2, al3, bh[ni][0], bh[ni][1]);
                MMA16816(acc[mi][ni], ah0, ah1, ah2, ah3, bl[ni][0], bl[ni][1]);
            }
        }
    }

    const int g = lane >> 2;
    const int t = lane & 3;
    #pragma unroll
    for (int mi = 0; mi < 2; mi++) {
        int r_hi = row0 + wm * 32 + mi * 16 + g;
        #pragma unroll
        for (int half = 0; half < 2; half++) {
            int r = r_hi + half * 8;
            if (r < M) {
                float* dst = C + (size_t)r * N + wn * WN + t * 2;
                #pragma unroll
                for (int ni = 0; ni < NF; ni++) {
                    float2 o = half ? make_float2(acc[mi][ni][2], acc[mi][ni][3])
                                    : make_float2(acc[mi][ni][0], acc[mi][ni][1]);
                    *reinterpret_cast<float2*>(dst + ni * 8) = o;
                }
            }
        }
    }
}

// ---------------- persistent tensor-core GEMM -----------------------------
// copies B once per CTA, then loops over 64-row tiles with A prefetch
template<int N>
__global__ void __launch_bounds__(256)
mma_gemm(const float* __restrict__ A0, const float* __restrict__ A1,
         const __nv_bfloat16* __restrict__ imgBh0, const __nv_bfloat16* __restrict__ imgBl0,
         const __nv_bfloat16* __restrict__ imgBh1, const __nv_bfloat16* __restrict__ imgBl1,
         float* __restrict__ C0, float* __restrict__ C1, int M) {
    constexpr int SA_STR = 136;
    constexpr int SB_STR = N + 8;
    constexpr int OFF_AH = 0;
    constexpr int OFF_AL = OFF_AH + 64 * SA_STR * 2;
    constexpr int OFF_BH = OFF_AL + 64 * SA_STR * 2;
    constexpr int BCNT   = 128 * SB_STR * 2 / 16;

    extern __shared__ __align__(16) char smem[];
    const uint32_t sbase = smem_u32(smem);

    const int tid  = threadIdx.x;
    const int wid  = tid >> 5;
    const int lane = tid & 31;
    const int wm   = wid >> 2;
    const int wn   = wid & 3;

    const float* A = blockIdx.y ? A1 : A0;
    const __nv_bfloat16* imgBh = blockIdx.y ? imgBh1 : imgBh0;
    const __nv_bfloat16* imgBl = blockIdx.y ? imgBl1 : imgBl0;
    float* C = blockIdx.y ? C1 : C0;

    // B images once per CTA
    {
        const int4* sh = reinterpret_cast<const int4*>(imgBh);
        const int4* sl = reinterpret_cast<const int4*>(imgBl);
        int4* dh = reinterpret_cast<int4*>(smem + OFF_BH);
        int4* dl = reinterpret_cast<int4*>(smem + OFF_BH + 128 * SB_STR * 2);
        #pragma unroll
        for (int i = tid; i < BCNT; i += 256) { dh[i] = sh[i]; dl[i] = sl[i]; }
    }

    const int nTiles = (M + 63) / 64;
    float4 av[8];
    int tile = blockIdx.x;
    if (tile < nTiles) load_A_regs(A, tile * 64, tid, M, av);

    for (; tile < nTiles; tile += gridDim.x) {
        __syncthreads();   // B ready (first iter) / prior compute done reading A
        sts_A(smem, OFF_AH, OFF_AL, tid, av);
        __syncthreads();
        int nt = tile + gridDim.x;
        if (nt < nTiles) load_A_regs(A, nt * 64, tid, M, av);
        tile_compute_store<N>(sbase, wm, wn, lane, tile * 64, M, C);
    }
}

// ---------------- host side ----------------
extern "C" void kernel_launch(void* const* d_in, const int* in_sizes, int n_in,
                              void* d_out, int out_size) {
    (void)in_sizes; (void)n_in; (void)out_size;

    const int*   q_rel     = (const int*)  d_in[1];
    const int*   q_tau     = (const int*)  d_in[2];
    const float* hidden    = (const float*)d_in[3];
    const int*   edges     = (const int*)  d_in[4];
    const float* rela      = (const float*)d_in[7];
    const float* Ws        = (const float*)d_in[8];
    const float* Wr        = (const float*)d_in[9];
    const float* Wqr       = (const float*)d_in[10];
    const float* Wqr_b     = (const float*)d_in[11];
    const float* Wtau      = (const float*)d_in[12];
    const float* w_alpha   = (const float*)d_in[13];
    const float* w_alpha_b = (const float*)d_in[14];
    const float* W_h       = (const float*)d_in[15];
    const float* W_h_s     = (const float*)d_in[16];
    const float* w_t1      = (const float*)d_in[17];
    const float* b_t1      = (const float*)d_in[18];
    const float* w_t2      = (const float*)d_in[19];
    const float* b_t2      = (const float*)d_in[20];
    float* out = (float*)d_out;

    void *p_hsW, *p_agg, *p_agg_s, *p_counts;
    void *p_WhH, *p_WhL, *p_WhsH, *p_WhsL, *p_WsH, *p_WsL;
    cudaGetSymbolAddress(&p_hsW,    d_hsW);
    cudaGetSymbolAddress(&p_agg,    d_agg);
    cudaGetSymbolAddress(&p_agg_s,  d_agg_s);
    cudaGetSymbolAddress(&p_counts, d_counts);
    cudaGetSymbolAddress(&p_WhH,  d_Wh_hi);
    cudaGetSymbolAddress(&p_WhL,  d_Wh_lo);
    cudaGetSymbolAddress(&p_WhsH, d_Whs_hi);
    cudaGetSymbolAddress(&p_WhsL, d_Whs_lo);
    cudaGetSymbolAddress(&p_WsH,  d_Ws_hi);
    cudaGetSymbolAddress(&p_WsL,  d_Ws_lo);

    const int SMEM128 = 34816 + 2 * 128 * 136 * 2;  // 104448
    const int SMEM64  = 34816 + 2 * 128 * 72 * 2;   //  71680
    cudaFuncSetAttribute(mma_gemm<128>, cudaFuncAttributeMaxDynamicSharedMemorySize, SMEM128);
    cudaFuncSetAttribute(mma_gemm<64>,  cudaFuncAttributeMaxDynamicSharedMemorySize, SMEM64);

    // ---- counting sort of edges by obj ----
    cudaMemsetAsync(p_counts, 0, N_NODE * sizeof(int));
    hist_kernel<<<(N_EDGE + 255) / 256, 256>>>(edges);
    scan1_kernel<<<N_SCANB, SCAN_B>>>();
    scan3_kernel<<<N_SCANB, SCAN_B>>>();
    fill_kernel<<<(N_EDGE + 255) / 256, 256>>>(edges);

    // ---- small tables + weight images ----
    table_kernel<<<N_RELTAB + N_Q + N_TAU, 128>>>(rela, q_rel, q_tau, Wr, Wqr, Wqr_b,
                                                  Wtau, w_t1, b_t1, w_t2, b_t2);
    wprep_kernel<<<128, 136>>>(W_h, W_h_s, Ws);

    // ---- hsW = hidden @ Ws (persistent, 2 CTAs/SM) ----
    mma_gemm<64><<<dim3(296, 1), 256, SMEM64>>>(
        hidden, nullptr,
        (const __nv_bfloat16*)p_WsH, (const __nv_bfloat16*)p_WsL,
        nullptr, nullptr,
        (float*)p_hsW, nullptr, N_NODE);

    // ---- attention alphas -> sorted records ----
    int nwarp = (N_EDGE + 1) / 2;
    int nblk  = (nwarp * 32 + 255) / 256;
    alpha_kernel<<<nblk, 256>>>(edges, w_alpha, w_alpha_b, q_tau);

    // ---- sorted aggregation ----
    agg_kernel<<<(N_NODE * 32 + 255) / 256, 256>>>(hidden, rela);

    // ---- output GEMMs (persistent, 2 CTAs/SM across y) ----
    mma_gemm<128><<<dim3(148, 2), 256, SMEM128>>>(
        (const float*)p_agg, (const float*)p_agg_s,
        (const __nv_bfloat16*)p_WhH, (const __nv_bfloat16*)p_WhL,
        (const __nv_bfloat16*)p_WhsH, (const __nv_bfloat16*)p_WhsL,
        out, out + N_NODE * OUT_DIM, N_NODE);
}